// round 6
// baseline (speedup 1.0000x reference)
#include <cuda_runtime.h>
#include <math.h>
#include <stdint.h>

// MoE router: logits = x @ W^T ([16384,2048] x [2048,8]), top-2 + softmax.
// Output layout (fp32): [indices 16384*2][gates 16384*2][logits 16384*8].
//
// x (128MB) is streamed via cp.async.bulk into per-warp double-buffered smem:
// the async copy engine guarantees deep MLP (the failure mode of all LDG
// variants). W (64KB) stays L1-resident via __ldg (smem=128KB leaves ~100KB
// L1). FMAs are packed f32x2 to keep the FMA pipe under 50%.

#define DDIM        2048
#define NEXP        8
#define TGRP        4
#define NWARP       4
#define THREADS     (NWARP * 32)
#define HALF_FLOATS 1024
#define HALF_BYTES  (HALF_FLOATS * 4)      // 4096
#define BUF_BYTES   (TGRP * HALF_BYTES)    // 16384
#define NBUF        (NWARP * 2)
#define SMEM_BUFS   (NBUF * BUF_BYTES)     // 131072
#define SMEM_TOTAL  (SMEM_BUFS + NBUF * 8)
#define NBLOCK      148
#define DSTEPS      8                      // 128-float steps per half-row

typedef unsigned long long u64;

__device__ __forceinline__ void ffma2(u64& d, u64 a, u64 b) {
    asm("fma.rn.f32x2 %0, %1, %2, %3;" : "=l"(d) : "l"(a), "l"(b), "l"(d));
}
__device__ __forceinline__ float f2_sum(u64 v) {
    float lo, hi;
    asm("mov.b64 {%0,%1}, %2;" : "=f"(lo), "=f"(hi) : "l"(v));
    return lo + hi;
}

__global__ __launch_bounds__(THREADS)
void router_kernel(const float* __restrict__ x,
                   const float* __restrict__ w,
                   float* __restrict__ out,
                   int n_tokens)
{
    extern __shared__ char smem[];
    const int lane = threadIdx.x & 31;
    const int wid  = threadIdx.x >> 5;

    const uint32_t smem_base = (uint32_t)__cvta_generic_to_shared(smem);
    const uint32_t mbar_base = smem_base + SMEM_BUFS;

    if (threadIdx.x == 0) {
        for (int b = 0; b < NBUF; b++)
            asm volatile("mbarrier.init.shared.b64 [%0], 1;"
                         :: "r"(mbar_base + b * 8) : "memory");
    }
    __syncthreads();

    const int groups_total = n_tokens / TGRP;            // 4096
    const int gwarp  = blockIdx.x * NWARP + wid;
    const int stride = gridDim.x * NWARP;
    const int ngroups = (groups_total > gwarp)
                      ? (groups_total - gwarp + stride - 1) / stride : 0;
    const int nslots = ngroups * 2;                      // 2 half-rows per group

    float* out_idx    = out;
    float* out_gate   = out + (size_t)n_tokens * 2;
    float* out_logits = out + (size_t)n_tokens * 4;

    // Per-warp issue of one slot (group-half) into this warp's buffer s&1.
    auto issue = [&](int s) {
        const int bi = (wid << 1) | (s & 1);
        const uint32_t mbar = mbar_base + bi * 8;
        const uint32_t dst  = smem_base + bi * BUF_BYTES;
        const int g = gwarp + (s >> 1) * stride;
        const int h = s & 1;
        const float* src = x + (size_t)(g * TGRP) * DDIM + h * HALF_FLOATS;
        if (lane == 0) {
            asm volatile("mbarrier.arrive.expect_tx.shared.b64 _, [%0], %1;"
                         :: "r"(mbar), "r"((uint32_t)BUF_BYTES) : "memory");
            #pragma unroll
            for (int t = 0; t < TGRP; t++) {
                asm volatile(
                    "cp.async.bulk.shared::cta.global.mbarrier::complete_tx::bytes"
                    " [%0], [%1], %2, [%3];"
                    :: "r"(dst + t * HALF_BYTES),
                       "l"(src + (size_t)t * DDIM),
                       "r"((uint32_t)HALF_BYTES),
                       "r"(mbar) : "memory");
            }
        }
    };

    auto wait_full = [&](int s) {
        const uint32_t mbar = mbar_base + (((wid << 1) | (s & 1))) * 8;
        const uint32_t parity = (uint32_t)((s >> 1) & 1);
        uint32_t done;
        asm volatile(
            "{\n\t.reg .pred p;\n\t"
            "mbarrier.try_wait.parity.acquire.cta.shared::cta.b64 p, [%1], %2;\n\t"
            "selp.b32 %0, 1, 0, p;\n\t}"
            : "=r"(done) : "r"(mbar), "r"(parity) : "memory");
        if (!done) {
            asm volatile(
                "{\n\t.reg .pred P1;\n\t"
                "WAIT_LOOP_%=:\n\t"
                "mbarrier.try_wait.parity.acquire.cta.shared::cta.b64 P1, [%0], %1, 0x989680;\n\t"
                "@P1 bra.uni WAIT_DONE_%=;\n\t"
                "bra.uni WAIT_LOOP_%=;\n\t"
                "WAIT_DONE_%=:\n\t}"
                :: "r"(mbar), "r"(parity) : "memory");
        }
    };

    if (nslots > 0) issue(0);
    if (nslots > 1) issue(1);

    u64 acc[TGRP][NEXP];

    for (int s = 0; s < nslots; s++) {
        wait_full(s);
        const int h  = s & 1;
        const int bi = (wid << 1) | h;
        const char* buf = smem + (size_t)bi * BUF_BYTES;

        if (h == 0) {
            #pragma unroll
            for (int t = 0; t < TGRP; t++)
                #pragma unroll
                for (int e = 0; e < NEXP; e++)
                    acc[t][e] = 0ull;
        }

        #pragma unroll 2
        for (int j = 0; j < DSTEPS; j++) {
            ulonglong2 xv[TGRP];
            #pragma unroll
            for (int t = 0; t < TGRP; t++)
                xv[t] = *reinterpret_cast<const ulonglong2*>(
                            buf + t * HALF_BYTES + j * 512 + lane * 16);
            #pragma unroll
            for (int e = 0; e < NEXP; e++) {
                ulonglong2 wv = __ldg(reinterpret_cast<const ulonglong2*>(
                    w + (size_t)e * DDIM + h * HALF_FLOATS + j * 128 + lane * 4));
                #pragma unroll
                for (int t = 0; t < TGRP; t++) {
                    ffma2(acc[t][e], xv[t].x, wv.x);
                    ffma2(acc[t][e], xv[t].y, wv.y);
                }
            }
        }

        if (h == 1) {
            const int g = gwarp + (s >> 1) * stride;
            const int tok0 = g * TGRP;

            float accs[TGRP][NEXP];
            #pragma unroll
            for (int t = 0; t < TGRP; t++) {
                #pragma unroll
                for (int e = 0; e < NEXP; e++) {
                    float v = f2_sum(acc[t][e]);
                    v += __shfl_xor_sync(0xffffffffu, v, 16);
                    v += __shfl_xor_sync(0xffffffffu, v, 8);
                    v += __shfl_xor_sync(0xffffffffu, v, 4);
                    v += __shfl_xor_sync(0xffffffffu, v, 2);
                    v += __shfl_xor_sync(0xffffffffu, v, 1);
                    accs[t][e] = v;
                }
            }

            if (lane < TGRP) {
                const int tok = tok0 + lane;
                // Predicated token select (no dynamic register indexing).
                float v[NEXP];
                #pragma unroll
                for (int e = 0; e < NEXP; e++) {
                    float sv = accs[0][e];
                    if (lane == 1) sv = accs[1][e];
                    if (lane == 2) sv = accs[2][e];
                    if (lane == 3) sv = accs[3][e];
                    v[e] = sv;
                }

                *reinterpret_cast<float4*>(out_logits + (size_t)tok * NEXP) =
                    make_float4(v[0], v[1], v[2], v[3]);
                *reinterpret_cast<float4*>(out_logits + (size_t)tok * NEXP + 4) =
                    make_float4(v[4], v[5], v[6], v[7]);

                // top-2 (ties -> lower index, matching jax.lax.top_k)
                int i0 = 0; float v0 = v[0];
                #pragma unroll
                for (int e = 1; e < NEXP; e++)
                    if (v[e] > v0) { v0 = v[e]; i0 = e; }
                int i1 = -1; float v1 = -INFINITY;
                #pragma unroll
                for (int e = 0; e < NEXP; e++)
                    if (e != i0 && v[e] > v1) { v1 = v[e]; i1 = e; }

                float ex = __expf(v1 - v0);
                float g0 = 1.0f / (1.0f + ex);
                float g1 = ex * g0;

                *reinterpret_cast<float2*>(out_idx  + (size_t)tok * 2) =
                    make_float2((float)i0, (float)i1);
                *reinterpret_cast<float2*>(out_gate + (size_t)tok * 2) =
                    make_float2(g0, g1);
            }
        }

        if (s + 2 < nslots) issue(s + 2);
    }
}

extern "C" void kernel_launch(void* const* d_in, const int* in_sizes, int n_in,
                              void* d_out, int out_size)
{
    const float* x = (const float*)d_in[0];
    const float* w = (const float*)d_in[1];
    float* out = (float*)d_out;

    const int n_tokens = in_sizes[0] / DDIM;   // 16384

    static int smem_set = 0;
    if (!smem_set) {
        cudaFuncSetAttribute(router_kernel,
                             cudaFuncAttributeMaxDynamicSharedMemorySize,
                             SMEM_TOTAL);
        smem_set = 1;
    }

    router_kernel<<<NBLOCK, THREADS, SMEM_TOTAL>>>(x, w, out, n_tokens);
}

// round 7
// speedup vs baseline: 1.2080x; 1.2080x over previous
#include <cuda_runtime.h>
#include <math.h>

// MoE router: logits = x @ W^T  ([16384,2048] x [2048,8]), top-2 + softmax.
// Output layout (fp32): [indices 16384*2][gates 16384*2][logits 16384*8].
//
// Structure of the best round (R2): one warp per 4 tokens, W (64KB)
// L1-resident, x streamed once. Change: inner product issued as packed
// fma.rn.f32x2 (FFMA2, rt matches 2x scalar FFMA) with loads left to the
// compiler (ulonglong2 derefs / __ldg) so ptxas can batch them -> fewer
// issue slots per DRAM byte, FMA pipe at ~48% instead of saturating.

#define DDIM 2048
#define NEXP 8
#define TGRP 4
#define CHUNKS (DDIM / 128)   // 16 chunks of 128 floats (4 per lane)

typedef unsigned long long u64;

// Packed dual FMA: d = a*b + d on both f32 halves (sm_103a FFMA2).
__device__ __forceinline__ void ffma2(u64& d, u64 a, u64 b) {
    asm("fma.rn.f32x2 %0, %1, %2, %3;" : "=l"(d) : "l"(a), "l"(b), "l"(d));
}
__device__ __forceinline__ float f2_sum(u64 v) {
    float lo, hi;
    asm("mov.b64 {%0,%1}, %2;" : "=f"(lo), "=f"(hi) : "l"(v));
    return lo + hi;
}

__global__ __launch_bounds__(256, 2)
void router_kernel(const float* __restrict__ x,
                   const float* __restrict__ w,
                   float* __restrict__ out,
                   int n_tokens, int groups_total)
{
    const int lane  = threadIdx.x & 31;
    const int warp  = (blockIdx.x * blockDim.x + threadIdx.x) >> 5;
    const int nwarp = (gridDim.x * blockDim.x) >> 5;

    float* out_idx    = out;
    float* out_gate   = out + (size_t)n_tokens * 2;
    float* out_logits = out + (size_t)n_tokens * 4;

    for (int g = warp; g < groups_total; g += nwarp) {
        const int tok0 = g * TGRP;
        const float* xp = x + (size_t)tok0 * DDIM + lane * 4;
        const float* wp = w + lane * 4;

        // acc[t][e]: f32x2 partial sums over (even,odd) positions of each
        // float4 lane-slice.
        u64 acc[TGRP][NEXP];
        #pragma unroll
        for (int t = 0; t < TGRP; t++)
            #pragma unroll
            for (int e = 0; e < NEXP; e++)
                acc[t][e] = 0ull;

        #pragma unroll 2
        for (int c = 0; c < CHUNKS; c++) {
            ulonglong2 xv[TGRP];
            #pragma unroll
            for (int t = 0; t < TGRP; t++)
                xv[t] = *reinterpret_cast<const ulonglong2*>(
                            xp + (size_t)t * DDIM + c * 128);
            #pragma unroll
            for (int e = 0; e < NEXP; e++) {
                ulonglong2 wv = __ldg(reinterpret_cast<const ulonglong2*>(
                                      wp + e * DDIM + c * 128));
                #pragma unroll
                for (int t = 0; t < TGRP; t++) {
                    ffma2(acc[t][e], xv[t].x, wv.x);
                    ffma2(acc[t][e], xv[t].y, wv.y);
                }
            }
        }

        // Collapse f32x2 halves, then full butterfly so every lane has sums.
        float accs[TGRP][NEXP];
        #pragma unroll
        for (int t = 0; t < TGRP; t++) {
            #pragma unroll
            for (int e = 0; e < NEXP; e++) {
                float v = f2_sum(acc[t][e]);
                v += __shfl_xor_sync(0xffffffffu, v, 16);
                v += __shfl_xor_sync(0xffffffffu, v, 8);
                v += __shfl_xor_sync(0xffffffffu, v, 4);
                v += __shfl_xor_sync(0xffffffffu, v, 2);
                v += __shfl_xor_sync(0xffffffffu, v, 1);
                accs[t][e] = v;
            }
        }

        if (lane < TGRP) {
            const int tok = tok0 + lane;
            // Select this lane's token via predicated moves (no dynamic
            // register indexing -> no local-memory spill).
            float v[NEXP];
            #pragma unroll
            for (int e = 0; e < NEXP; e++) {
                float s = accs[0][e];
                if (lane == 1) s = accs[1][e];
                if (lane == 2) s = accs[2][e];
                if (lane == 3) s = accs[3][e];
                v[e] = s;
            }

            // logits (two 16B stores)
            *reinterpret_cast<float4*>(out_logits + (size_t)tok * NEXP) =
                make_float4(v[0], v[1], v[2], v[3]);
            *reinterpret_cast<float4*>(out_logits + (size_t)tok * NEXP + 4) =
                make_float4(v[4], v[5], v[6], v[7]);

            // top-2 (ties -> lower index, matching jax.lax.top_k)
            int i0 = 0; float v0 = v[0];
            #pragma unroll
            for (int e = 1; e < NEXP; e++)
                if (v[e] > v0) { v0 = v[e]; i0 = e; }
            int i1 = -1; float v1 = -INFINITY;
            #pragma unroll
            for (int e = 0; e < NEXP; e++)
                if (e != i0 && v[e] > v1) { v1 = v[e]; i1 = e; }

            // softmax over [v0, v1] with v0 = max
            float ex = __expf(v1 - v0);
            float g0 = 1.0f / (1.0f + ex);
            float g1 = ex * g0;

            *reinterpret_cast<float2*>(out_idx  + (size_t)tok * 2) =
                make_float2((float)i0, (float)i1);
            *reinterpret_cast<float2*>(out_gate + (size_t)tok * 2) =
                make_float2(g0, g1);
        }
    }
}

extern "C" void kernel_launch(void* const* d_in, const int* in_sizes, int n_in,
                              void* d_out, int out_size)
{
    const float* x = (const float*)d_in[0];
    const float* w = (const float*)d_in[1];
    float* out = (float*)d_out;

    const int n_tokens = in_sizes[0] / DDIM;     // 16384
    const int groups   = n_tokens / TGRP;        // 4096

    router_kernel<<<256, 256>>>(x, w, out, n_tokens, groups);
}